// round 15
// baseline (speedup 1.0000x reference)
#include <cuda_runtime.h>
#include <cuda_bf16.h>
#include <cstdint>
#include <cstddef>

// Problem dims: x [4,2048,4096] -> M=8192, K=4096; w [16384,4096] -> N=16384
#define MDIM 8192
#define KDIM 4096
#define NDIM 16384
#define MAXV 448.0f
#define EPSV 1e-12f

#define XAB 1024
#define WAB 2048

// ---------------- device scratch ----------------
__device__ float g_part[XAB + WAB];
__device__ float g_scales[3];                       // sx, sw, 1/(sx*sw)
__device__ uint8_t g_xq[(size_t)MDIM * KDIM];       // 32 MB e4m3 (scaled domain)
__device__ uint8_t g_wq[(size_t)NDIM * KDIM];       // 64 MB e4m3 (scaled domain)

// ---------------- launch 1: fused amax partials ----------------
__global__ void amax_fused_kernel(const float4* __restrict__ x, const float4* __restrict__ w) {
    __shared__ float sred[16];
    int seg = (blockIdx.x < XAB) ? 0 : 1;
    const float4* p = seg ? w : x;
    size_t n4 = seg ? ((size_t)NDIM * KDIM / 4) : ((size_t)MDIM * KDIM / 4);
    int b = seg ? (blockIdx.x - XAB) : blockIdx.x;
    size_t nb = seg ? WAB : XAB;

    float m0 = 0.f, m1 = 0.f, m2 = 0.f, m3 = 0.f;
    size_t stride = nb * blockDim.x;
    for (size_t i = (size_t)b * blockDim.x + threadIdx.x; i < n4; i += stride) {
        float4 v = p[i];
        m0 = fmaxf(m0, fabsf(v.x));
        m1 = fmaxf(m1, fabsf(v.y));
        m2 = fmaxf(m2, fabsf(v.z));
        m3 = fmaxf(m3, fabsf(v.w));
    }
    float m = fminf(fmaxf(fmaxf(m0, m1), fmaxf(m2, m3)), MAXV);
#pragma unroll
    for (int o = 16; o > 0; o >>= 1) m = fmaxf(m, __shfl_xor_sync(0xffffffffu, m, o));
    if ((threadIdx.x & 31) == 0) sred[threadIdx.x >> 5] = m;
    __syncthreads();
    if (threadIdx.x == 0) {
        float r = sred[0];
        int nw = blockDim.x >> 5;
        for (int i = 1; i < nw; ++i) r = fmaxf(r, sred[i]);
        g_part[blockIdx.x] = r;
    }
}

// ---------------- launch 2: reduce partials -> scales ----------------
__global__ void scales_kernel() {
    __shared__ float sx_s[32], sw_s[32];
    int t = threadIdx.x, lane = t & 31, wrp = t >> 5;
    float mx = 0.f, mw = 0.f;
    for (int i = t; i < XAB; i += 1024) mx = fmaxf(mx, g_part[i]);
    for (int i = t; i < WAB; i += 1024) mw = fmaxf(mw, g_part[XAB + i]);
#pragma unroll
    for (int o = 16; o > 0; o >>= 1) {
        mx = fmaxf(mx, __shfl_xor_sync(0xffffffffu, mx, o));
        mw = fmaxf(mw, __shfl_xor_sync(0xffffffffu, mw, o));
    }
    if (lane == 0) { sx_s[wrp] = mx; sw_s[wrp] = mw; }
    __syncthreads();
    if (t == 0) {
        float ax = EPSV, aw = EPSV;
#pragma unroll
        for (int i = 0; i < 32; ++i) { ax = fmaxf(ax, sx_s[i]); aw = fmaxf(aw, sw_s[i]); }
        float sx = MAXV / ax, sw = MAXV / aw;
        g_scales[0] = sx;
        g_scales[1] = sw;
        g_scales[2] = (1.f / sx) * (1.f / sw);
    }
}

// ---------------- direct e4m3 quantize: clamp -> scale -> cvt.rn.satfinite ----------------
__device__ __forceinline__ uint32_t quant4(float4 v, float s) {
    float a = fminf(fmaxf(v.x, -MAXV), MAXV) * s;
    float b = fminf(fmaxf(v.y, -MAXV), MAXV) * s;
    float c = fminf(fmaxf(v.z, -MAXV), MAXV) * s;
    float d = fminf(fmaxf(v.w, -MAXV), MAXV) * s;
    uint16_t lo, hi;
    asm("cvt.rn.satfinite.e4m3x2.f32 %0, %2, %1;" : "=h"(lo) : "f"(a), "f"(b));
    asm("cvt.rn.satfinite.e4m3x2.f32 %0, %2, %1;" : "=h"(hi) : "f"(c), "f"(d));
    return (uint32_t)lo | ((uint32_t)hi << 16);
}

// ---------------- launch 3: fused quantize ----------------
#define QXB 1024
#define QWB 2048
__global__ void quant_fused_kernel(const float4* __restrict__ x, const float4* __restrict__ w) {
    int seg = (blockIdx.x < QXB) ? 0 : 1;
    const float4* in = seg ? w : x;
    uint32_t* outq = (uint32_t*)(seg ? g_wq : g_xq);
    size_t n4 = seg ? ((size_t)NDIM * KDIM / 4) : ((size_t)MDIM * KDIM / 4);
    int b = seg ? (blockIdx.x - QXB) : blockIdx.x;
    size_t nb = seg ? QWB : QXB;
    float s = g_scales[seg];
    size_t stride = nb * blockDim.x;
    size_t i = (size_t)b * blockDim.x + threadIdx.x;
    for (; i + stride < n4; i += 2 * stride) {
        float4 v0 = in[i];
        float4 v1 = in[i + stride];
        uint32_t q0 = quant4(v0, s);
        uint32_t q1 = quant4(v1, s);
        outq[i] = q0;
        outq[i + stride] = q1;
    }
    if (i < n4) outq[i] = quant4(in[i], s);
}

// =======================================================================
// launch 4: persistent FP8 mma.sync GEMM. CTA 128x128, warp tile 64x64,
// BK=64, 4-stage cp.async. Grid=296 (2/SM); each CTA loops over tiles and
// issues the NEXT tile's prologue loads before the current epilogue.
// =======================================================================
#define BM 128
#define BN 128
#define BK 64
#define STAGES 4
#define NKIT (KDIM / BK)            // 64
#define PITCHB 80
#define TILE_B (128 * PITCHB)       // 10240
#define STAGE_B (2 * TILE_B)        // 20480
#define SMEM_TOT (STAGES * STAGE_B) // 81920
#define NTILES ((MDIM / BM) * (NDIM / BN))   // 8192
#define GGRID 296                   // 148 SMs * 2 CTAs

__device__ __forceinline__ uint32_t smem_u32(const void* p) {
    return (uint32_t)__cvta_generic_to_shared(p);
}
__device__ __forceinline__ void cp16s(uint32_t dst, const void* src) {
    asm volatile("cp.async.cg.shared.global [%0], [%1], 16;\n" :: "r"(dst), "l"(src));
}
__device__ __forceinline__ void ldsm_x4(uint32_t* r, uint32_t addr) {
    asm volatile("ldmatrix.sync.aligned.m8n8.x4.shared.b16 {%0,%1,%2,%3}, [%4];\n"
                 : "=r"(r[0]), "=r"(r[1]), "=r"(r[2]), "=r"(r[3]) : "r"(addr));
}
__device__ __forceinline__ void mma_fp8(float* c, const uint32_t* a, const uint32_t* b) {
    asm volatile("mma.sync.aligned.m16n8k32.row.col.f32.e4m3.e4m3.f32 "
                 "{%0,%1,%2,%3}, {%4,%5,%6,%7}, {%8,%9}, {%0,%1,%2,%3};\n"
                 : "+f"(c[0]), "+f"(c[1]), "+f"(c[2]), "+f"(c[3])
                 : "r"(a[0]), "r"(a[1]), "r"(a[2]), "r"(a[3]), "r"(b[0]), "r"(b[1]));
}

__device__ __forceinline__ void load_stage(uint8_t* smem, int s,
                                           const uint8_t* __restrict__ gA,
                                           const uint8_t* __restrict__ gB,
                                           int k0, int tid) {
    uint32_t stA = smem_u32(smem + (size_t)s * STAGE_B);
    uint32_t stB = stA + TILE_B;
#pragma unroll
    for (int j = 0; j < 8; ++j) {
        int chunk = j * 128 + tid;
        if (j < 4) {
            int r = chunk >> 2, c = (chunk & 3) * 16;
            cp16s(stA + r * PITCHB + c, gA + (size_t)r * KDIM + k0 + c);
        } else {
            int bc = chunk - 512;
            int r = bc >> 2, c = (bc & 3) * 16;
            cp16s(stB + r * PITCHB + c, gB + (size_t)r * KDIM + k0 + c);
        }
    }
    asm volatile("cp.async.commit_group;\n" ::: "memory");
}

__device__ __forceinline__ void load_frags(uint32_t stA, uint32_t stB, int wm, int wn,
                                           int lane, int ks,
                                           uint32_t a[4][4], uint32_t b[8][2]) {
#pragma unroll
    for (int i = 0; i < 4; ++i) {
        uint32_t addr = stA + (wm + i * 16 + (lane & 15)) * PITCHB
                            + ks * 32 + (lane >> 4) * 16;
        ldsm_x4(a[i], addr);
    }
#pragma unroll
    for (int jj = 0; jj < 4; ++jj) {
        int g = lane >> 3;
        int row = wn + jj * 16 + ((g >> 1) << 3) + (lane & 7);
        int col = ks * 32 + ((g & 1) << 4);
        uint32_t r[4];
        ldsm_x4(r, stB + row * PITCHB + col);
        b[2 * jj][0] = r[0]; b[2 * jj][1] = r[1];
        b[2 * jj + 1][0] = r[2]; b[2 * jj + 1][1] = r[3];
    }
}

__global__ void __launch_bounds__(128, 2)
gemm_fp8_kernel(const float* __restrict__ bias, float* __restrict__ out) {
    extern __shared__ uint8_t smem[];

    int tid = threadIdx.x;
    int lane = tid & 31, warp = tid >> 5;
    int wm = (warp >> 1) * 64;
    int wn = (warp & 1) * 64;

    // prefetch prologue of the first tile
    {
        int t0 = blockIdx.x;
        const uint8_t* gA0 = g_xq + (size_t)(t0 & 63) * BM * KDIM;
        const uint8_t* gB0 = g_wq + (size_t)(t0 >> 6) * BN * KDIM;
        load_stage(smem, 0, gA0, gB0, 0, tid);
        load_stage(smem, 1, gA0, gB0, BK, tid);
        load_stage(smem, 2, gA0, gB0, 2 * BK, tid);
    }

    for (int t = blockIdx.x; t < NTILES; t += GGRID) {
        int mblk = t & 63, nblk = t >> 6;
        const uint8_t* gA = g_xq + (size_t)mblk * BM * KDIM;
        const uint8_t* gB = g_wq + (size_t)nblk * BN * KDIM;

        float acc[4][8][4];
#pragma unroll
        for (int i = 0; i < 4; ++i)
#pragma unroll
            for (int j = 0; j < 8; ++j)
#pragma unroll
                for (int k = 0; k < 4; ++k) acc[i][j][k] = 0.f;

        // stage 0 complete (own groups) + visible (barrier) for iter 0 pre-read
        asm volatile("cp.async.wait_group 2;\n" ::: "memory");
        __syncthreads();

        for (int kt = 0; kt < NKIT; ++kt) {
            uint32_t stA = smem_u32(smem + (size_t)(kt & (STAGES - 1)) * STAGE_B);
            uint32_t stB = stA + TILE_B;

            // ks0 fragments before the barrier (stage kt guaranteed by the
            // previous iteration's wait + barrier)
            uint32_t a[4][4], b[8][2];
            load_frags(stA, stB, wm, wn, lane, 0, a, b);

            // need stage kt+1 complete before this barrier; near the tail
            // (no more commits in flight) drain fully to close the window
            if (kt < NKIT - 2)
                asm volatile("cp.async.wait_group 1;\n" ::: "memory");
            else
                asm volatile("cp.async.wait_group 0;\n" ::: "memory");
            __syncthreads();

            if (kt + 3 < NKIT)
                load_stage(smem, (kt + 3) & (STAGES - 1), gA, gB, (kt + 3) * BK, tid);

#pragma unroll
            for (int i = 0; i < 4; ++i)
#pragma unroll
                for (int j = 0; j < 8; ++j)
                    mma_fp8(acc[i][j], a[i], b[j]);

            load_frags(stA, stB, wm, wn, lane, 1, a, b);
#pragma unroll
            for (int i = 0; i < 4; ++i)
#pragma unroll
                for (int j = 0; j < 8; ++j)
                    mma_fp8(acc[i][j], a[i], b[j]);
        }

        // issue NEXT tile's prologue before the epilogue: DRAM latency hides
        // under the stores. Writes slots 0-2; post-last-barrier reads touch
        // only slot 3, so no cross-warp hazard.
        if (t + GGRID < NTILES) {
            int tn = t + GGRID;
            const uint8_t* gAn = g_xq + (size_t)(tn & 63) * BM * KDIM;
            const uint8_t* gBn = g_wq + (size_t)(tn >> 6) * BN * KDIM;
            load_stage(smem, 0, gAn, gBn, 0, tid);
            load_stage(smem, 1, gAn, gBn, BK, tid);
            load_stage(smem, 2, gAn, gBn, 2 * BK, tid);
        }

        // epilogue
        float inv = g_scales[2];
        int m0 = mblk * BM + wm;
        int n0 = nblk * BN + wn;
#pragma unroll
        for (int i = 0; i < 4; ++i) {
            int m = m0 + i * 16 + (lane >> 2);
#pragma unroll
            for (int j = 0; j < 8; ++j) {
                int n = n0 + j * 8 + ((lane & 3) << 1);
                float b0 = __ldg(&bias[n]), b1 = __ldg(&bias[n + 1]);
                float2 v0 = make_float2(acc[i][j][0] * inv + b0, acc[i][j][1] * inv + b1);
                float2 v1 = make_float2(acc[i][j][2] * inv + b0, acc[i][j][3] * inv + b1);
                *reinterpret_cast<float2*>(&out[(size_t)m * NDIM + n]) = v0;
                *reinterpret_cast<float2*>(&out[(size_t)(m + 8) * NDIM + n]) = v1;
            }
        }
    }
}

// ---------------- 4 launches; GEMM is launch #4 (profiled slot) ----------------
extern "C" void kernel_launch(void* const* d_in, const int* in_sizes, int n_in,
                              void* d_out, int out_size) {
    const float* x    = (const float*)d_in[0];
    const float* w    = (const float*)d_in[1];
    const float* bias = (const float*)d_in[2];
    float* out = (float*)d_out;

    amax_fused_kernel<<<XAB + WAB, 512>>>((const float4*)x, (const float4*)w);
    scales_kernel<<<1, 1024>>>();
    quant_fused_kernel<<<QXB + QWB, 512>>>((const float4*)x, (const float4*)w);

    static bool attr_done = false;
    if (!attr_done) {
        cudaFuncSetAttribute(gemm_fp8_kernel,
                             cudaFuncAttributeMaxDynamicSharedMemorySize, SMEM_TOT);
        attr_done = true;
    }
    gemm_fp8_kernel<<<GGRID, 128, SMEM_TOT>>>(bias, out);
}

// round 16
// speedup vs baseline: 1.1909x; 1.1909x over previous
#include <cuda_runtime.h>
#include <cuda_bf16.h>
#include <cstdint>
#include <cstddef>

// Problem dims: x [4,2048,4096] -> M=8192, K=4096; w [16384,4096] -> N=16384
#define MDIM 8192
#define KDIM 4096
#define NDIM 16384
#define MAXV 448.0f
#define EPSV 1e-12f

#define XAB 1024
#define WAB 2048

// ---------------- device scratch ----------------
__device__ float g_part[XAB + WAB];
__device__ float g_scales[3];                       // sx, sw, 1/(sx*sw)
__device__ uint8_t g_xq[(size_t)MDIM * KDIM];       // 32 MB e4m3 (scaled domain)
__device__ uint8_t g_wq[(size_t)NDIM * KDIM];       // 64 MB e4m3 (scaled domain)

// ---------------- launch 1: fused amax partials ----------------
__global__ void amax_fused_kernel(const float4* __restrict__ x, const float4* __restrict__ w) {
    __shared__ float sred[16];
    int seg = (blockIdx.x < XAB) ? 0 : 1;
    const float4* p = seg ? w : x;
    size_t n4 = seg ? ((size_t)NDIM * KDIM / 4) : ((size_t)MDIM * KDIM / 4);
    int b = seg ? (blockIdx.x - XAB) : blockIdx.x;
    size_t nb = seg ? WAB : XAB;

    float m0 = 0.f, m1 = 0.f, m2 = 0.f, m3 = 0.f;
    size_t stride = nb * blockDim.x;
    for (size_t i = (size_t)b * blockDim.x + threadIdx.x; i < n4; i += stride) {
        float4 v = p[i];
        m0 = fmaxf(m0, fabsf(v.x));
        m1 = fmaxf(m1, fabsf(v.y));
        m2 = fmaxf(m2, fabsf(v.z));
        m3 = fmaxf(m3, fabsf(v.w));
    }
    float m = fminf(fmaxf(fmaxf(m0, m1), fmaxf(m2, m3)), MAXV);
#pragma unroll
    for (int o = 16; o > 0; o >>= 1) m = fmaxf(m, __shfl_xor_sync(0xffffffffu, m, o));
    if ((threadIdx.x & 31) == 0) sred[threadIdx.x >> 5] = m;
    __syncthreads();
    if (threadIdx.x == 0) {
        float r = sred[0];
        int nw = blockDim.x >> 5;
        for (int i = 1; i < nw; ++i) r = fmaxf(r, sred[i]);
        g_part[blockIdx.x] = r;
    }
}

// ---------------- launch 2: reduce partials -> scales ----------------
__global__ void scales_kernel() {
    __shared__ float sx_s[32], sw_s[32];
    int t = threadIdx.x, lane = t & 31, wrp = t >> 5;
    float mx = 0.f, mw = 0.f;
    for (int i = t; i < XAB; i += 1024) mx = fmaxf(mx, g_part[i]);
    for (int i = t; i < WAB; i += 1024) mw = fmaxf(mw, g_part[XAB + i]);
#pragma unroll
    for (int o = 16; o > 0; o >>= 1) {
        mx = fmaxf(mx, __shfl_xor_sync(0xffffffffu, mx, o));
        mw = fmaxf(mw, __shfl_xor_sync(0xffffffffu, mw, o));
    }
    if (lane == 0) { sx_s[wrp] = mx; sw_s[wrp] = mw; }
    __syncthreads();
    if (t == 0) {
        float ax = EPSV, aw = EPSV;
#pragma unroll
        for (int i = 0; i < 32; ++i) { ax = fmaxf(ax, sx_s[i]); aw = fmaxf(aw, sw_s[i]); }
        float sx = MAXV / ax, sw = MAXV / aw;
        g_scales[0] = sx;
        g_scales[1] = sw;
        g_scales[2] = (1.f / sx) * (1.f / sw);
    }
}

// ---------------- direct e4m3 quantize: clamp -> scale -> cvt.rn.satfinite ----------------
__device__ __forceinline__ uint32_t quant4(float4 v, float s) {
    float a = fminf(fmaxf(v.x, -MAXV), MAXV) * s;
    float b = fminf(fmaxf(v.y, -MAXV), MAXV) * s;
    float c = fminf(fmaxf(v.z, -MAXV), MAXV) * s;
    float d = fminf(fmaxf(v.w, -MAXV), MAXV) * s;
    uint16_t lo, hi;
    asm("cvt.rn.satfinite.e4m3x2.f32 %0, %2, %1;" : "=h"(lo) : "f"(a), "f"(b));
    asm("cvt.rn.satfinite.e4m3x2.f32 %0, %2, %1;" : "=h"(hi) : "f"(c), "f"(d));
    return (uint32_t)lo | ((uint32_t)hi << 16);
}

// ---------------- launch 3: fused quantize ----------------
#define QXB 1024
#define QWB 2048
__global__ void quant_fused_kernel(const float4* __restrict__ x, const float4* __restrict__ w) {
    int seg = (blockIdx.x < QXB) ? 0 : 1;
    const float4* in = seg ? w : x;
    uint32_t* outq = (uint32_t*)(seg ? g_wq : g_xq);
    size_t n4 = seg ? ((size_t)NDIM * KDIM / 4) : ((size_t)MDIM * KDIM / 4);
    int b = seg ? (blockIdx.x - QXB) : blockIdx.x;
    size_t nb = seg ? QWB : QXB;
    float s = g_scales[seg];
    size_t stride = nb * blockDim.x;
    size_t i = (size_t)b * blockDim.x + threadIdx.x;
    for (; i + stride < n4; i += 2 * stride) {
        float4 v0 = in[i];
        float4 v1 = in[i + stride];
        uint32_t q0 = quant4(v0, s);
        uint32_t q1 = quant4(v1, s);
        outq[i] = q0;
        outq[i + stride] = q1;
    }
    if (i < n4) outq[i] = quant4(in[i], s);
}

// =======================================================================
// launch 4: FP8 mma.sync GEMM (R14 structure; protocol-correct tail wait;
// streaming output stores). CTA 128x128, warp tile 64x64, BK=64, 4 stages.
// =======================================================================
#define BM 128
#define BN 128
#define BK 64
#define STAGES 4
#define NKIT (KDIM / BK)            // 64
#define PITCHB 80
#define TILE_B (128 * PITCHB)       // 10240
#define STAGE_B (2 * TILE_B)        // 20480
#define SMEM_TOT (STAGES * STAGE_B) // 81920

__device__ __forceinline__ uint32_t smem_u32(const void* p) {
    return (uint32_t)__cvta_generic_to_shared(p);
}
__device__ __forceinline__ void cp16s(uint32_t dst, const void* src) {
    asm volatile("cp.async.cg.shared.global [%0], [%1], 16;\n" :: "r"(dst), "l"(src));
}
__device__ __forceinline__ void ldsm_x4(uint32_t* r, uint32_t addr) {
    asm volatile("ldmatrix.sync.aligned.m8n8.x4.shared.b16 {%0,%1,%2,%3}, [%4];\n"
                 : "=r"(r[0]), "=r"(r[1]), "=r"(r[2]), "=r"(r[3]) : "r"(addr));
}
__device__ __forceinline__ void mma_fp8(float* c, const uint32_t* a, const uint32_t* b) {
    asm volatile("mma.sync.aligned.m16n8k32.row.col.f32.e4m3.e4m3.f32 "
                 "{%0,%1,%2,%3}, {%4,%5,%6,%7}, {%8,%9}, {%0,%1,%2,%3};\n"
                 : "+f"(c[0]), "+f"(c[1]), "+f"(c[2]), "+f"(c[3])
                 : "r"(a[0]), "r"(a[1]), "r"(a[2]), "r"(a[3]), "r"(b[0]), "r"(b[1]));
}
__device__ __forceinline__ void st_cs_v2(float* p, float a, float b) {
    asm volatile("st.global.cs.v2.f32 [%0], {%1,%2};\n" :: "l"(p), "f"(a), "f"(b) : "memory");
}

__device__ __forceinline__ void load_stage(uint8_t* smem, int s,
                                           const uint8_t* __restrict__ gA,
                                           const uint8_t* __restrict__ gB,
                                           int k0, int tid) {
    uint32_t stA = smem_u32(smem + (size_t)s * STAGE_B);
    uint32_t stB = stA + TILE_B;
#pragma unroll
    for (int j = 0; j < 8; ++j) {
        int chunk = j * 128 + tid;
        if (j < 4) {
            int r = chunk >> 2, c = (chunk & 3) * 16;
            cp16s(stA + r * PITCHB + c, gA + (size_t)r * KDIM + k0 + c);
        } else {
            int bc = chunk - 512;
            int r = bc >> 2, c = (bc & 3) * 16;
            cp16s(stB + r * PITCHB + c, gB + (size_t)r * KDIM + k0 + c);
        }
    }
    asm volatile("cp.async.commit_group;\n" ::: "memory");
}

__device__ __forceinline__ void load_frags(uint32_t stA, uint32_t stB, int wm, int wn,
                                           int lane, int ks,
                                           uint32_t a[4][4], uint32_t b[8][2]) {
#pragma unroll
    for (int i = 0; i < 4; ++i) {
        uint32_t addr = stA + (wm + i * 16 + (lane & 15)) * PITCHB
                            + ks * 32 + (lane >> 4) * 16;
        ldsm_x4(a[i], addr);
    }
#pragma unroll
    for (int jj = 0; jj < 4; ++jj) {
        int g = lane >> 3;
        int row = wn + jj * 16 + ((g >> 1) << 3) + (lane & 7);
        int col = ks * 32 + ((g & 1) << 4);
        uint32_t r[4];
        ldsm_x4(r, stB + row * PITCHB + col);
        b[2 * jj][0] = r[0]; b[2 * jj][1] = r[1];
        b[2 * jj + 1][0] = r[2]; b[2 * jj + 1][1] = r[3];
    }
}

__global__ void __launch_bounds__(128, 2)
gemm_fp8_kernel(const float* __restrict__ bias, float* __restrict__ out) {
    extern __shared__ uint8_t smem[];

    int tid = threadIdx.x;
    int lane = tid & 31, warp = tid >> 5;
    int wm = (warp >> 1) * 64;
    int wn = (warp & 1) * 64;
    int mblk = blockIdx.x, nblk = blockIdx.y;

    const uint8_t* gA = g_xq + (size_t)mblk * BM * KDIM;
    const uint8_t* gB = g_wq + (size_t)nblk * BN * KDIM;

    float acc[4][8][4];
#pragma unroll
    for (int i = 0; i < 4; ++i)
#pragma unroll
        for (int j = 0; j < 8; ++j)
#pragma unroll
            for (int k = 0; k < 4; ++k) acc[i][j][k] = 0.f;

    load_stage(smem, 0, gA, gB, 0, tid);
    load_stage(smem, 1, gA, gB, BK, tid);
    load_stage(smem, 2, gA, gB, 2 * BK, tid);

    // stage 0 complete + visible for iter 0's pre-barrier ldsm
    asm volatile("cp.async.wait_group 2;\n" ::: "memory");
    __syncthreads();

    for (int kt = 0; kt < NKIT; ++kt) {
        uint32_t stA = smem_u32(smem + (size_t)(kt & (STAGES - 1)) * STAGE_B);
        uint32_t stB = stA + TILE_B;

        // ks0 fragments before the barrier: stage kt complete (previous
        // iteration's wait) and visible (previous barrier); latency hides
        // under the barrier wait.
        uint32_t a[4][4], b[8][2];
        load_frags(stA, stB, wm, wn, lane, 0, a, b);

        // need stage kt+1 complete before this barrier (next iter's
        // pre-barrier ldsm). Steady state: 3 groups in flight, wait_group 1
        // -> stages <= kt+1 done. Tail (no more commits): drain fully.
        if (kt < NKIT - 2)
            asm volatile("cp.async.wait_group 1;\n" ::: "memory");
        else
            asm volatile("cp.async.wait_group 0;\n" ::: "memory");
        __syncthreads();

        if (kt + 3 < NKIT)
            load_stage(smem, (kt + 3) & (STAGES - 1), gA, gB, (kt + 3) * BK, tid);

#pragma unroll
        for (int i = 0; i < 4; ++i)
#pragma unroll
            for (int j = 0; j < 8; ++j)
                mma_fp8(acc[i][j], a[i], b[j]);

        // ks1 fragments (reuse regs), then second MMA batch
        load_frags(stA, stB, wm, wn, lane, 1, a, b);
#pragma unroll
        for (int i = 0; i < 4; ++i)
#pragma unroll
            for (int j = 0; j < 8; ++j)
                mma_fp8(acc[i][j], a[i], b[j]);
    }

    float inv = g_scales[2];
    int m0 = mblk * BM + wm;
    int n0 = nblk * BN + wn;
#pragma unroll
    for (int i = 0; i < 4; ++i) {
        int m = m0 + i * 16 + (lane >> 2);
#pragma unroll
        for (int j = 0; j < 8; ++j) {
            int n = n0 + j * 8 + ((lane & 3) << 1);
            float b0 = __ldg(&bias[n]), b1 = __ldg(&bias[n + 1]);
            // streaming stores: output is never re-read; keep A/B panels in L2
            st_cs_v2(&out[(size_t)m * NDIM + n],
                     acc[i][j][0] * inv + b0, acc[i][j][1] * inv + b1);
            st_cs_v2(&out[(size_t)(m + 8) * NDIM + n],
                     acc[i][j][2] * inv + b0, acc[i][j][3] * inv + b1);
        }
    }
}

// ---------------- 4 launches; GEMM is launch #4 (profiled slot) ----------------
extern "C" void kernel_launch(void* const* d_in, const int* in_sizes, int n_in,
                              void* d_out, int out_size) {
    const float* x    = (const float*)d_in[0];
    const float* w    = (const float*)d_in[1];
    const float* bias = (const float*)d_in[2];
    float* out = (float*)d_out;

    amax_fused_kernel<<<XAB + WAB, 512>>>((const float4*)x, (const float4*)w);
    scales_kernel<<<1, 1024>>>();
    quant_fused_kernel<<<QXB + QWB, 512>>>((const float4*)x, (const float4*)w);

    static bool attr_done = false;
    if (!attr_done) {
        cudaFuncSetAttribute(gemm_fp8_kernel,
                             cudaFuncAttributeMaxDynamicSharedMemorySize, SMEM_TOT);
        attr_done = true;
    }
    dim3 grid(MDIM / BM, NDIM / BN);   // (64, 128): M fastest; A panel L2-resident
    gemm_fp8_kernel<<<grid, 128, SMEM_TOT>>>(bias, out);
}